// round 4
// baseline (speedup 1.0000x reference)
#include <cuda_runtime.h>

// out[i] = sum_b sum_j x1[b,j] * x2[b,(i-j) mod 1024]
// Polyphase: out[2m+e] = sum_n x1[2n]  * x2[(2(m-n)+e)     & 1023]
//                      + sum_n x1[2n+1]* x2[(2(m-n)+e - 1) & 1023]
// Even-phase pairs live in sE = x2; shifted pairs in sR[k] = x2[(k-1)&1023].
// Both are even-aligned float2s -> FFMA2 with zero packing movs.

#define BSZ 128
#define D   1024

typedef unsigned long long u64;

__device__ float g_partial[BSZ * D];
__device__ unsigned g_counter = 0;

__device__ __forceinline__ u64 pk(float x, float y) {
    float2 v = make_float2(x, y);
    return *reinterpret_cast<u64*>(&v);
}
__device__ __forceinline__ u64 pk2(float2 v) { return *reinterpret_cast<u64*>(&v); }
__device__ __forceinline__ u64 fma_x2(u64 a, u64 b, u64 c) {
    u64 d;
    asm("fma.rn.f32x2 %0, %1, %2, %3;" : "=l"(d) : "l"(a), "l"(b), "l"(c));
    return d;
}

__global__ void __launch_bounds__(128, 1)
conv_fused_kernel(const float* __restrict__ x1, const float* __restrict__ x2,
                  float* __restrict__ out) {
    __shared__ __align__(16) float s1d[2 * D];  // s1d[2j]=s1d[2j+1]=x1[j]
    __shared__ __align__(16) float sE[D];       // x2
    __shared__ __align__(16) float sR[D];       // x2 rotated: sR[k]=x2[(k-1)&1023]
    __shared__ float red[128];

    const int b   = blockIdx.x;
    const int tid = threadIdx.x;

    // ---- stage ----
    {
        const float4* x1v = reinterpret_cast<const float4*>(x1 + b * D);
        const float4* x2v = reinterpret_cast<const float4*>(x2 + b * D);
        float4* s1v = reinterpret_cast<float4*>(s1d);
        float4* sEv = reinterpret_cast<float4*>(sE);
        #pragma unroll
        for (int q = tid; q < D / 4; q += 128) {
            const float4 v1 = x1v[q];
            s1v[2 * q    ] = make_float4(v1.x, v1.x, v1.y, v1.y);
            s1v[2 * q + 1] = make_float4(v1.z, v1.z, v1.w, v1.w);
            const float4 v2 = x2v[q];
            sEv[q] = v2;
            sR[(4 * q + 1)         ] = v2.x;
            sR[(4 * q + 2)         ] = v2.y;
            sR[(4 * q + 3)         ] = v2.z;
            sR[(4 * q + 4) & (D-1) ] = v2.w;
        }
    }
    __syncthreads();

    const float4*  s1d4 = reinterpret_cast<const float4*>(s1d);
    const float2*  sE2  = reinterpret_cast<const float2*>(sE);
    const float2*  sR2  = reinterpret_cast<const float2*>(sR);
    const float4*  sE4  = reinterpret_cast<const float4*>(sE);
    const float4*  sR4  = reinterpret_cast<const float4*>(sR);

    const int m0 = tid * 4;      // pair index; this thread owns outputs 8t..8t+7
    u64 P0 = 0, P1 = 0, P2 = 0, P3 = 0;

    // Windows over pair-index space (mod 512): W[w] = s?2[(base + w) & 511],
    // base = m0 - 4c - 4 at chunk c. Slides by 4 pairs per chunk.
    float2 WE[8], WR[8];
    {
        #pragma unroll
        for (int h = 0; h < 4; h++) {
            const int p = (m0 - 4 + 2 * h) & 511;     // even, no float4 straddle
            const float4 e = sE4[p >> 1];
            const float4 r = sR4[p >> 1];
            WE[2*h] = make_float2(e.x, e.y); WE[2*h+1] = make_float2(e.z, e.w);
            WR[2*h] = make_float2(r.x, r.y); WR[2*h+1] = make_float2(r.z, r.w);
        }
    }

    #pragma unroll 2
    for (int c = 0; c < 128; c++) {
        const int base = m0 - 4 * c - 4;

        #pragma unroll
        for (int s = 0; s < 4; s++) {
            const int n = 4 * c + s;
            const float4 av = s1d4[n];              // broadcast: dup(x1[2n]), dup(x1[2n+1])
            const u64 ae = pk(av.x, av.y);
            const u64 ao = pk(av.z, av.w);
            // slot w = 4 - s + k for accumulator k
            P0 = fma_x2(ae, pk2(WE[4 - s    ]), P0);
            P1 = fma_x2(ae, pk2(WE[4 - s + 1]), P1);
            P2 = fma_x2(ae, pk2(WE[4 - s + 2]), P2);
            P3 = fma_x2(ae, pk2(WE[4 - s + 3]), P3);
            P0 = fma_x2(ao, pk2(WR[4 - s    ]), P0);
            P1 = fma_x2(ao, pk2(WR[4 - s + 1]), P1);
            P2 = fma_x2(ao, pk2(WR[4 - s + 2]), P2);
            P3 = fma_x2(ao, pk2(WR[4 - s + 3]), P3);
        }

        // refill for next chunk: new base' = base - 4
        const int p0 = (base - 4) & 511;            // multiple of 4
        const int p1 = (base - 2) & 511;
        const float4 e0 = sE4[p0 >> 1], e1 = sE4[p1 >> 1];
        const float4 r0 = sR4[p0 >> 1], r1 = sR4[p1 >> 1];
        WE[7] = WE[3]; WE[6] = WE[2]; WE[5] = WE[1]; WE[4] = WE[0];
        WR[7] = WR[3]; WR[6] = WR[2]; WR[5] = WR[1]; WR[4] = WR[0];
        WE[0] = make_float2(e0.x, e0.y); WE[1] = make_float2(e0.z, e0.w);
        WE[2] = make_float2(e1.x, e1.y); WE[3] = make_float2(e1.z, e1.w);
        WR[0] = make_float2(r0.x, r0.y); WR[1] = make_float2(r0.z, r0.w);
        WR[2] = make_float2(r1.x, r1.y); WR[3] = make_float2(r1.z, r1.w);
    }

    // store 8 outputs: out[2m0 + 0..7] for this batch
    {
        const float2 q0 = *reinterpret_cast<float2*>(&P0);
        const float2 q1 = *reinterpret_cast<float2*>(&P1);
        const float2 q2 = *reinterpret_cast<float2*>(&P2);
        const float2 q3 = *reinterpret_cast<float2*>(&P3);
        float4* dst = reinterpret_cast<float4*>(&g_partial[b * D + 2 * m0]);
        dst[0] = make_float4(q0.x, q0.y, q1.x, q1.y);
        dst[1] = make_float4(q2.x, q2.y, q3.x, q3.y);
    }

    // ---- cross-CTA barrier (replay-safe ticket) ----
    __syncthreads();
    if (tid == 0) {
        __threadfence();
        const unsigned old    = atomicAdd(&g_counter, 1u);
        const unsigned target = old - (old & (BSZ - 1)) + BSZ;
        unsigned cur;
        do {
            asm volatile("ld.global.acquire.gpu.u32 %0, [%1];"
                         : "=r"(cur) : "l"(&g_counter));
        } while ((int)(cur - target) < 0);
    }
    __syncthreads();

    // ---- fused reduction: CTA b owns outputs [8b, 8b+8) ----
    {
        const int i    = blockIdx.x * 8 + (tid & 7);
        const int brow = tid >> 3;  // 0..15
        float s = 0.f;
        #pragma unroll
        for (int k = 0; k < 8; k++)
            s += __ldcg(&g_partial[(brow + 16 * k) * D + i]);
        red[tid] = s;
        __syncthreads();
        if (tid < 8) {
            float t = 0.f;
            #pragma unroll
            for (int g = 0; g < 16; g++) t += red[tid + 8 * g];
            out[blockIdx.x * 8 + tid] = t;
        }
    }
}

extern "C" void kernel_launch(void* const* d_in, const int* in_sizes, int n_in,
                              void* d_out, int out_size) {
    const float* x1  = (const float*)d_in[0];  // (128, 1024) fp32
    const float* x2  = (const float*)d_in[1];  // (128, 1024) fp32
    float*       out = (float*)d_out;          // (1,1,1024) fp32

    conv_fused_kernel<<<BSZ, 128>>>(x1, x2, out);
}

// round 5
// speedup vs baseline: 1.2909x; 1.2909x over previous
#include <cuda_runtime.h>

// out[i] = sum_b sum_j x1[b,j] * x2[b,(i-j) mod 1024]
// Scalar FFMA conv (R2 body, proven at fma floor) + fused cross-CTA
// ticket barrier + in-kernel reduction (R3 epilogue, proven).

#define BSZ 128
#define D   1024
#define DMASK 1023

__device__ float g_partial[BSZ * D];
__device__ unsigned g_counter = 0;

__global__ void __launch_bounds__(256, 1)
conv_fused_kernel(const float* __restrict__ x1, const float* __restrict__ x2,
                  float* __restrict__ out) {
    __shared__ __align__(16) float s1[D];
    __shared__ __align__(16) float s2[D];
    __shared__ float red[256];

    const int b   = blockIdx.x;
    const int tid = threadIdx.x;

    // ---- stage ----
    const float4* x1v = reinterpret_cast<const float4*>(x1 + b * D);
    const float4* x2v = reinterpret_cast<const float4*>(x2 + b * D);
    reinterpret_cast<float4*>(s1)[tid] = x1v[tid];
    reinterpret_cast<float4*>(s2)[tid] = x2v[tid];
    __syncthreads();

    const int i0 = tid * 4;  // this thread owns outputs i0..i0+3

    float acc0 = 0.f, acc1 = 0.f, acc2 = 0.f, acc3 = 0.f;

    // Sliding window W[k] = s2[(base + k) & DMASK]; 16B-aligned quad loads
    // never straddle the circular wrap.
    float W[8];
    {
        float4 w0 = *reinterpret_cast<const float4*>(&s2[(i0 - 4) & DMASK]);
        float4 w1 = *reinterpret_cast<const float4*>(&s2[i0]);
        W[0] = w0.x; W[1] = w0.y; W[2] = w0.z; W[3] = w0.w;
        W[4] = w1.x; W[5] = w1.y; W[6] = w1.z; W[7] = w1.w;
    }

    #pragma unroll 8
    for (int j = 0; j < D; j += 4) {
        const float4 a = *reinterpret_cast<const float4*>(&s1[j]);  // broadcast

        acc0 += a.x * W[4]; acc1 += a.x * W[5]; acc2 += a.x * W[6]; acc3 += a.x * W[7];
        acc0 += a.y * W[3]; acc1 += a.y * W[4]; acc2 += a.y * W[5]; acc3 += a.y * W[6];
        acc0 += a.z * W[2]; acc1 += a.z * W[3]; acc2 += a.z * W[4]; acc3 += a.z * W[5];
        acc0 += a.w * W[1]; acc1 += a.w * W[2]; acc2 += a.w * W[3]; acc3 += a.w * W[4];

        const float4 nw = *reinterpret_cast<const float4*>(&s2[(i0 - j - 8) & DMASK]);
        W[4] = W[0]; W[5] = W[1]; W[6] = W[2]; W[7] = W[3];
        W[0] = nw.x; W[1] = nw.y; W[2] = nw.z; W[3] = nw.w;
    }

    *reinterpret_cast<float4*>(&g_partial[b * D + i0]) =
        make_float4(acc0, acc1, acc2, acc3);

    // ---- cross-CTA barrier (replay-safe monotonic ticket) ----
    __syncthreads();
    if (tid == 0) {
        __threadfence();  // release g_partial writes
        const unsigned old    = atomicAdd(&g_counter, 1u);
        const unsigned target = old - (old & (BSZ - 1)) + BSZ;
        unsigned cur;
        do {
            asm volatile("ld.global.acquire.gpu.u32 %0, [%1];"
                         : "=r"(cur) : "l"(&g_counter));
        } while ((int)(cur - target) < 0);
    }
    __syncthreads();

    // ---- fused deterministic reduction: CTA b owns outputs [8b, 8b+8) ----
    {
        const int i    = blockIdx.x * 8 + (tid & 7);
        const int brow = tid >> 3;  // 0..31
        float s = __ldcg(&g_partial[(brow      ) * D + i])
                + __ldcg(&g_partial[(brow + 32 ) * D + i])
                + __ldcg(&g_partial[(brow + 64 ) * D + i])
                + __ldcg(&g_partial[(brow + 96 ) * D + i]);
        red[tid] = s;
        __syncthreads();
        if (tid < 8) {
            float t = 0.f;
            #pragma unroll
            for (int m = 0; m < 32; m++) t += red[tid + 8 * m];
            out[blockIdx.x * 8 + tid] = t;
        }
    }
}

extern "C" void kernel_launch(void* const* d_in, const int* in_sizes, int n_in,
                              void* d_out, int out_size) {
    const float* x1  = (const float*)d_in[0];  // (128, 1024) fp32
    const float* x2  = (const float*)d_in[1];  // (128, 1024) fp32
    float*       out = (float*)d_out;          // (1,1,1024) fp32

    conv_fused_kernel<<<BSZ, 256>>>(x1, x2, out);
}

// round 6
// speedup vs baseline: 1.2937x; 1.0022x over previous
#include <cuda_runtime.h>

// out[i] = sum_b sum_j x1[b,j] * x2[b,(i-j) mod 1024]
// Scalar FFMA conv at the fma floor + fused cross-CTA reduction.
// R6 change: ticket-barrier polling uses __nanosleep backoff to kill
// L2 contention on the counter line.

#define BSZ 128
#define D   1024
#define DMASK 1023

__device__ float g_partial[BSZ * D];
__device__ unsigned g_counter = 0;

__global__ void __launch_bounds__(256, 1)
conv_fused_kernel(const float* __restrict__ x1, const float* __restrict__ x2,
                  float* __restrict__ out) {
    __shared__ __align__(16) float s1[D];
    __shared__ __align__(16) float s2[D];
    __shared__ float red[256];

    const int b   = blockIdx.x;
    const int tid = threadIdx.x;

    // ---- stage ----
    const float4* x1v = reinterpret_cast<const float4*>(x1 + b * D);
    const float4* x2v = reinterpret_cast<const float4*>(x2 + b * D);
    reinterpret_cast<float4*>(s1)[tid] = x1v[tid];
    reinterpret_cast<float4*>(s2)[tid] = x2v[tid];
    __syncthreads();

    const int i0 = tid * 4;  // this thread owns outputs i0..i0+3

    float acc0 = 0.f, acc1 = 0.f, acc2 = 0.f, acc3 = 0.f;

    // Sliding window W[k] = s2[(base + k) & DMASK]; 16B-aligned quad loads
    // never straddle the circular wrap.
    float W[8];
    {
        float4 w0 = *reinterpret_cast<const float4*>(&s2[(i0 - 4) & DMASK]);
        float4 w1 = *reinterpret_cast<const float4*>(&s2[i0]);
        W[0] = w0.x; W[1] = w0.y; W[2] = w0.z; W[3] = w0.w;
        W[4] = w1.x; W[5] = w1.y; W[6] = w1.z; W[7] = w1.w;
    }

    #pragma unroll 8
    for (int j = 0; j < D; j += 4) {
        const float4 a = *reinterpret_cast<const float4*>(&s1[j]);  // broadcast

        acc0 += a.x * W[4]; acc1 += a.x * W[5]; acc2 += a.x * W[6]; acc3 += a.x * W[7];
        acc0 += a.y * W[3]; acc1 += a.y * W[4]; acc2 += a.y * W[5]; acc3 += a.y * W[6];
        acc0 += a.z * W[2]; acc1 += a.z * W[3]; acc2 += a.z * W[4]; acc3 += a.z * W[5];
        acc0 += a.w * W[1]; acc1 += a.w * W[2]; acc2 += a.w * W[3]; acc3 += a.w * W[4];

        const float4 nw = *reinterpret_cast<const float4*>(&s2[(i0 - j - 8) & DMASK]);
        W[4] = W[0]; W[5] = W[1]; W[6] = W[2]; W[7] = W[3];
        W[0] = nw.x; W[1] = nw.y; W[2] = nw.z; W[3] = nw.w;
    }

    *reinterpret_cast<float4*>(&g_partial[b * D + i0]) =
        make_float4(acc0, acc1, acc2, acc3);

    // ---- cross-CTA barrier: monotonic ticket + nanosleep backoff ----
    __syncthreads();
    if (tid == 0) {
        __threadfence();  // release g_partial writes
        const unsigned old    = atomicAdd(&g_counter, 1u);
        const unsigned target = old - (old & (BSZ - 1)) + BSZ;
        unsigned cur;
        asm volatile("ld.global.acquire.gpu.u32 %0, [%1];"
                     : "=r"(cur) : "l"(&g_counter));
        unsigned ns = 128;
        while ((int)(cur - target) < 0) {
            __nanosleep(ns);
            if (ns < 1024) ns <<= 1;
            asm volatile("ld.global.acquire.gpu.u32 %0, [%1];"
                         : "=r"(cur) : "l"(&g_counter));
        }
    }
    __syncthreads();

    // ---- fused deterministic reduction: CTA b owns outputs [8b, 8b+8) ----
    {
        const int i    = blockIdx.x * 8 + (tid & 7);
        const int brow = tid >> 3;  // 0..31
        float s = __ldcg(&g_partial[(brow      ) * D + i])
                + __ldcg(&g_partial[(brow + 32 ) * D + i])
                + __ldcg(&g_partial[(brow + 64 ) * D + i])
                + __ldcg(&g_partial[(brow + 96 ) * D + i]);
        red[tid] = s;
        __syncthreads();
        if (tid < 8) {
            float t = 0.f;
            #pragma unroll
            for (int m = 0; m < 32; m++) t += red[tid + 8 * m];
            out[blockIdx.x * 8 + tid] = t;
        }
    }
}

extern "C" void kernel_launch(void* const* d_in, const int* in_sizes, int n_in,
                              void* d_out, int out_size) {
    const float* x1  = (const float*)d_in[0];  // (128, 1024) fp32
    const float* x2  = (const float*)d_in[1];  // (128, 1024) fp32
    float*       out = (float*)d_out;          // (1,1,1024) fp32

    conv_fused_kernel<<<BSZ, 256>>>(x1, x2, out);
}

// round 7
// speedup vs baseline: 1.5478x; 1.1964x over previous
#include <cuda_runtime.h>

// out[i] = sum_b sum_j x1[b,j] * x2[b,(i-j) mod 1024]  (circular conv, summed over b)
// FFT method: Z_b = FFT(x1_b + i*x2_b); unpack X1,X2; P_b = X1.*X2;
// S = sum_b P_b; out = (1/N) * Re(IDFT(S)).

#define BSZ 128
#define D   1024
#define DMASK 1023

__device__ float2  g_P[BSZ * D];  // per-batch spectrum products (1 MB)
__device__ float2  g_S[D];        // reduced spectrum
__device__ unsigned g_counter = 0;

__global__ void __launch_bounds__(256, 1)
fftconv_kernel(const float* __restrict__ x1, const float* __restrict__ x2,
               float* __restrict__ out) {
    __shared__ float2 bufA[D];
    __shared__ float2 bufB[D];
    __shared__ float2 roots[D];   // roots[m] = e^{+2*pi*i*m/1024}
    __shared__ float2 sS[D];
    __shared__ float2 red[256];

    const int b   = blockIdx.x;
    const int tid = threadIdx.x;

    // ---- root table (also provides FFT twiddles via conj) ----
    #pragma unroll
    for (int m = tid; m < D; m += 256) {
        const float mm = (m >= D / 2) ? (float)(m - D) : (float)m;  // arg in [-pi, pi)
        float s, c;
        __sincosf(6.283185307179586f * (mm * (1.0f / D)), &s, &c);
        roots[m] = make_float2(c, s);
    }

    // ---- load & pack z = x1 + i*x2 ----
    {
        const float4 v1 = reinterpret_cast<const float4*>(x1 + b * D)[tid];
        const float4 v2 = reinterpret_cast<const float4*>(x2 + b * D)[tid];
        bufA[4 * tid + 0] = make_float2(v1.x, v2.x);
        bufA[4 * tid + 1] = make_float2(v1.y, v2.y);
        bufA[4 * tid + 2] = make_float2(v1.z, v2.z);
        bufA[4 * tid + 3] = make_float2(v1.w, v2.w);
    }
    __syncthreads();

    // ---- Stockham radix-2 FFT, 10 stages, auto-sorting ----
    // stage p: Ns = 2^p; butterfly j: base=j&(Ns-1), grp=j>>p
    //   a = src[j]; bb = src[j+512]; w = e^{-2pi*i*base/(2Ns)} = conj(roots[base<<(9-p)])
    //   dst[grp*2Ns+base] = a + bb*w ; dst[grp*2Ns+base+Ns] = a - bb*w
    float2* src = bufA;
    float2* dst = bufB;
    #pragma unroll
    for (int p = 0; p < 10; p++) {
        const int Ns = 1 << p;
        #pragma unroll
        for (int u = 0; u < 2; u++) {
            const int j    = tid + u * 256;          // 0..511
            const int base = j & (Ns - 1);
            const int grp  = j >> p;
            const float2 a  = src[j];
            const float2 bb = src[j + 512];
            const float2 w  = roots[base << (9 - p)];
            const float tr = bb.x * w.x + bb.y * w.y;   // bb * conj(w)
            const float ti = bb.y * w.x - bb.x * w.y;
            const int o = grp * 2 * Ns + base;
            dst[o]      = make_float2(a.x + tr, a.y + ti);
            dst[o + Ns] = make_float2(a.x - tr, a.y - ti);
        }
        __syncthreads();
        float2* t = src; src = dst; dst = t;
    }
    // result (natural order) now in src

    // ---- unpack real spectra & pointwise product ----
    // Z[k]=(a,b), Z[(N-k)%N]=(c,d):
    //   X1 = 0.5*(a+c, b-d), X2 = 0.5*(b+d, c-a), P = X1*X2
    #pragma unroll
    for (int u = 0; u < 4; u++) {
        const int k = tid + u * 256;
        const float2 zk = src[k];
        const float2 zm = src[(D - k) & DMASK];
        const float a = zk.x, bb = zk.y, c = zm.x, d = zm.y;
        const float x1r = a + c,  x1i = bb - d;
        const float x2r = bb + d, x2i = c - a;
        const float pr = 0.25f * (x1r * x2r - x1i * x2i);
        const float pi = 0.25f * (x1r * x2i + x1i * x2r);
        g_P[b * D + k] = make_float2(pr, pi);
    }

    // ---- barrier 1 (monotonic ticket; counter advances 256 per launch) ----
    __syncthreads();
    if (tid == 0) {
        __threadfence();
        const unsigned old    = atomicAdd(&g_counter, 1u);
        const unsigned target = old - (old & (BSZ - 1)) + BSZ;
        unsigned cur;
        do {
            asm volatile("ld.global.acquire.gpu.u32 %0, [%1];"
                         : "=r"(cur) : "l"(&g_counter));
        } while ((int)(cur - target) < 0);
    }
    __syncthreads();

    // ---- distributed reduce: CTA c owns freqs [8c, 8c+8) ----
    {
        const int k    = blockIdx.x * 8 + (tid & 7);
        const int brow = tid >> 3;  // 0..31
        float2 s0 = __ldcg(&g_P[(brow      ) * D + k]);
        float2 s1 = __ldcg(&g_P[(brow + 32 ) * D + k]);
        float2 s2 = __ldcg(&g_P[(brow + 64 ) * D + k]);
        float2 s3 = __ldcg(&g_P[(brow + 96 ) * D + k]);
        red[tid] = make_float2(s0.x + s1.x + s2.x + s3.x,
                               s0.y + s1.y + s2.y + s3.y);
        __syncthreads();
        if (tid < 8) {
            float2 t = make_float2(0.f, 0.f);
            #pragma unroll
            for (int m = 0; m < 32; m++) {
                t.x += red[tid + 8 * m].x;
                t.y += red[tid + 8 * m].y;
            }
            g_S[blockIdx.x * 8 + tid] = t;
        }
    }

    // ---- barrier 2 ----
    __syncthreads();
    if (tid == 0) {
        __threadfence();
        const unsigned old    = atomicAdd(&g_counter, 1u);
        const unsigned target = old - (old & (BSZ - 1)) + BSZ;
        unsigned cur;
        do {
            asm volatile("ld.global.acquire.gpu.u32 %0, [%1];"
                         : "=r"(cur) : "l"(&g_counter));
        } while ((int)(cur - target) < 0);
    }
    __syncthreads();

    // ---- load full reduced spectrum ----
    #pragma unroll
    for (int u = 0; u < 4; u++) {
        const int k = tid + u * 256;
        sS[k] = __ldcg(&g_S[k]);
    }
    __syncthreads();

    // ---- direct IDFT: warp w computes out[8c + w] ----
    {
        const int w    = tid >> 5;
        const int lane = tid & 31;
        const int i    = blockIdx.x * 8 + w;
        float acc = 0.f;
        #pragma unroll
        for (int q = 0; q < 32; q++) {
            const int k = lane + 32 * q;
            const float2 S = sS[k];
            const float2 e = roots[(k * i) & DMASK];  // e^{+2pi*i*k*i/N}
            acc += S.x * e.x - S.y * e.y;             // Re(S * e)
        }
        #pragma unroll
        for (int m = 16; m > 0; m >>= 1)
            acc += __shfl_xor_sync(0xFFFFFFFFu, acc, m);
        if (lane == 0) out[i] = acc * (1.0f / D);
    }
}

extern "C" void kernel_launch(void* const* d_in, const int* in_sizes, int n_in,
                              void* d_out, int out_size) {
    const float* x1  = (const float*)d_in[0];  // (128, 1024) fp32
    const float* x2  = (const float*)d_in[1];  // (128, 1024) fp32
    float*       out = (float*)d_out;          // (1,1,1024) fp32

    fftconv_kernel<<<BSZ, 256>>>(x1, x2, out);
}

// round 8
// speedup vs baseline: 2.1317x; 1.3772x over previous
#include <cuda_runtime.h>

// out[i] = sum_b sum_j x1[b,j] * x2[b,(i-j) mod 1024]
// Per-CTA: Z = FFT(x1 + i*x2) [radix-4 Stockham, 5 stages]; unpack -> P = X1.*X2;
// y_b = Re IDFT(P) in-CTA [radix-4 inverse]; write y_b.
// ONE global ticket barrier, then distributed sum over b (proven R5 epilogue).

#define BSZ 128
#define D   1024
#define DMASK 1023

__device__ float    g_partial[BSZ * D];
__device__ unsigned g_counter = 0;

__device__ __forceinline__ float2 cmul(float2 a, float2 w) {   // a * w
    return make_float2(a.x * w.x - a.y * w.y, a.x * w.y + a.y * w.x);
}
__device__ __forceinline__ float2 cmulc(float2 a, float2 w) {  // a * conj(w)
    return make_float2(a.x * w.x + a.y * w.y, a.y * w.x - a.x * w.y);
}
__device__ __forceinline__ float2 cadd(float2 a, float2 b) { return make_float2(a.x + b.x, a.y + b.y); }
__device__ __forceinline__ float2 csub(float2 a, float2 b) { return make_float2(a.x - b.x, a.y - b.y); }

// One fused radix-4 Stockham stage (covers radix-2 stages p and p+1).
// 256 threads, one butterfly each. INV=false: DFT (conj twiddles, -i);
// INV=true: unnormalized IDFT (+ twiddles, +i).
template <bool INV>
__device__ __forceinline__ void r4_step(const float2* __restrict__ src,
                                        float2* __restrict__ dst,
                                        const float2* __restrict__ roots,
                                        int p, int tid) {
    const int Ns = 1 << p;
    const int k  = tid & (Ns - 1);
    const int g2 = tid >> p;

    const float2 s0 = src[tid];
    const float2 s1 = src[tid + 256];
    const float2 s2 = src[tid + 512];
    const float2 s3 = src[tid + 768];

    const float2 w = roots[k << (9 - p)];
    const float2 v = roots[k << (8 - p)];

    const float2 m2 = INV ? cmul(s2, w) : cmulc(s2, w);
    const float2 m3 = INV ? cmul(s3, w) : cmulc(s3, w);
    const float2 t0 = cadd(s0, m2), t1 = csub(s0, m2);
    const float2 t2 = cadd(s1, m3), t3 = csub(s1, m3);

    const float2 a2 = INV ? cmul(t2, v) : cmulc(t2, v);
    const float2 x  = INV ? cmul(t3, v) : cmulc(t3, v);
    const float2 jx = INV ? make_float2(-x.y, x.x)    // +i*x
                          : make_float2(x.y, -x.x);   // -i*x

    const int o = g2 * 4 * Ns + k;
    dst[o]          = cadd(t0, a2);
    dst[o + Ns]     = cadd(t1, jx);
    dst[o + 2 * Ns] = csub(t0, a2);
    dst[o + 3 * Ns] = csub(t1, jx);
}

__global__ void __launch_bounds__(256, 1)
fftconv2_kernel(const float* __restrict__ x1, const float* __restrict__ x2,
                float* __restrict__ out) {
    __shared__ float2 bufA[D];
    __shared__ float2 bufB[D];
    __shared__ float2 roots[D];   // roots[m] = e^{+2*pi*i*m/1024}
    __shared__ float  red[256];

    const int b   = blockIdx.x;
    const int tid = threadIdx.x;

    // ---- root table ----
    #pragma unroll
    for (int m = tid; m < D; m += 256) {
        const float mm = (m >= D / 2) ? (float)(m - D) : (float)m;  // arg in [-pi,pi)
        float s, c;
        __sincosf(6.283185307179586f * (mm * (1.0f / D)), &s, &c);
        roots[m] = make_float2(c, s);
    }

    // ---- load & pack z = x1 + i*x2 ----
    {
        const float4 v1 = reinterpret_cast<const float4*>(x1 + b * D)[tid];
        const float4 v2 = reinterpret_cast<const float4*>(x2 + b * D)[tid];
        bufA[4 * tid + 0] = make_float2(v1.x, v2.x);
        bufA[4 * tid + 1] = make_float2(v1.y, v2.y);
        bufA[4 * tid + 2] = make_float2(v1.z, v2.z);
        bufA[4 * tid + 3] = make_float2(v1.w, v2.w);
    }
    __syncthreads();

    // ---- forward FFT: 5 radix-4 stages (p = 0,2,4,6,8), A->B->A->B->A->B ----
    r4_step<false>(bufA, bufB, roots, 0, tid); __syncthreads();
    r4_step<false>(bufB, bufA, roots, 2, tid); __syncthreads();
    r4_step<false>(bufA, bufB, roots, 4, tid); __syncthreads();
    r4_step<false>(bufB, bufA, roots, 6, tid); __syncthreads();
    r4_step<false>(bufA, bufB, roots, 8, tid); __syncthreads();
    // natural-order DFT now in bufB

    // ---- unpack real spectra & pointwise product -> bufA ----
    // Z[k]=(a,b), Z[(N-k)%N]=(c,d):
    //   X1 = 0.5*(a+c, b-d), X2 = 0.5*(b+d, c-a), P = X1*X2
    #pragma unroll
    for (int u = 0; u < 4; u++) {
        const int k = tid + u * 256;
        const float2 zk = bufB[k];
        const float2 zm = bufB[(D - k) & DMASK];
        const float a = zk.x, bb = zk.y, c = zm.x, d = zm.y;
        const float x1r = a + c,  x1i = bb - d;
        const float x2r = bb + d, x2i = c - a;
        bufA[k] = make_float2(0.25f * (x1r * x2r - x1i * x2i),
                              0.25f * (x1r * x2i + x1i * x2r));
    }
    __syncthreads();

    // ---- inverse FFT on P: 5 radix-4 stages, A->B->A->B->A->B ----
    r4_step<true>(bufA, bufB, roots, 0, tid); __syncthreads();
    r4_step<true>(bufB, bufA, roots, 2, tid); __syncthreads();
    r4_step<true>(bufA, bufB, roots, 4, tid); __syncthreads();
    r4_step<true>(bufB, bufA, roots, 6, tid); __syncthreads();
    r4_step<true>(bufA, bufB, roots, 8, tid); __syncthreads();
    // unnormalized IDFT in bufB; y_b[n] = bufB[n].x / 1024 (real by construction)

    {
        const int n = 4 * tid;
        *reinterpret_cast<float4*>(&g_partial[b * D + n]) =
            make_float4(bufB[n].x     * (1.0f / D),
                        bufB[n + 1].x * (1.0f / D),
                        bufB[n + 2].x * (1.0f / D),
                        bufB[n + 3].x * (1.0f / D));
    }

    // ---- single cross-CTA barrier (monotonic ticket) ----
    __syncthreads();
    if (tid == 0) {
        __threadfence();  // release g_partial writes
        const unsigned old    = atomicAdd(&g_counter, 1u);
        const unsigned target = old - (old & (BSZ - 1)) + BSZ;
        unsigned cur;
        do {
            asm volatile("ld.global.acquire.gpu.u32 %0, [%1];"
                         : "=r"(cur) : "l"(&g_counter));
        } while ((int)(cur - target) < 0);
    }
    __syncthreads();

    // ---- fused deterministic reduction: CTA c owns outputs [8c, 8c+8) ----
    {
        const int i    = blockIdx.x * 8 + (tid & 7);
        const int brow = tid >> 3;  // 0..31
        float s = __ldcg(&g_partial[(brow      ) * D + i])
                + __ldcg(&g_partial[(brow + 32 ) * D + i])
                + __ldcg(&g_partial[(brow + 64 ) * D + i])
                + __ldcg(&g_partial[(brow + 96 ) * D + i]);
        red[tid] = s;
        __syncthreads();
        if (tid < 8) {
            float t = 0.f;
            #pragma unroll
            for (int m = 0; m < 32; m++) t += red[tid + 8 * m];
            out[blockIdx.x * 8 + tid] = t;
        }
    }
}

extern "C" void kernel_launch(void* const* d_in, const int* in_sizes, int n_in,
                              void* d_out, int out_size) {
    const float* x1  = (const float*)d_in[0];  // (128, 1024) fp32
    const float* x2  = (const float*)d_in[1];  // (128, 1024) fp32
    float*       out = (float*)d_out;          // (1,1,1024) fp32

    fftconv2_kernel<<<BSZ, 256>>>(x1, x2, out);
}